// round 12
// baseline (speedup 1.0000x reference)
#include <cuda_runtime.h>
#include <cuda_bf16.h>
#include <cstdint>

// ---------------- problem constants ----------------
#define B_   16
#define C_   64
#define H_   192
#define W_   192
#define NPIX (H_ * W_)

// ---------------- tiling (R5 geometry) ----------------
#define TR 8                   // tile rows
#define TC 32                  // tile cols (256 px, 64 oc per tile)
#define HR 10                  // halo rows
#define HC 34                  // halo cols
#define ROWB  272              // 34 * 8 B (word pair e0,e1)
#define SLOTB (HR * ROWB)      // 2720 B per (kf,p) slot
#define IMGB  (16 * SLOTB)     // 43520 B per image (hi or lo)
#define SMEM_BYTES (2 * IMGB)  // 87040 B (hi, lo) -> 1 CTA/SM, ~141 KB L1 left
#define THREADS 512            // 16 warps: (row 0-7) x (oc-half 0-1)
#define TPC 16                 // tiles per CTA (persistent, same batch)

// Pre-packed W fragments: [b][tap][kf][hl][mf][lane] uint4 (mma A-frag order)
__device__ uint4 g_wfrag[B_ * 9 * 4 * 2 * 4 * 32];

// ---------------- helpers ----------------
__device__ __forceinline__ uint32_t smem_u32(const void* p) {
    uint32_t a;
    asm("{ .reg .u64 t; cvta.to.shared.u64 t, %1; cvt.u32.u64 %0, t; }" : "=r"(a) : "l"(p));
    return a;
}
__device__ __forceinline__ uint32_t cvt2(float lo, float hi) {
    uint32_t r;
    asm("cvt.rn.satfinite.bf16x2.f32 %0, %1, %2;" : "=r"(r) : "f"(hi), "f"(lo));
    return r;
}
__device__ __forceinline__ void split2(float v0, float v1, uint32_t& h2, uint32_t& l2) {
    h2 = cvt2(v0, v1);
    float h0 = __uint_as_float(h2 << 16);
    float h1 = __uint_as_float(h2 & 0xFFFF0000u);
    l2 = cvt2(v0 - h0, v1 - h1);
}
__device__ __forceinline__ void mma16816(float* c, const uint4& a, uint32_t b0, uint32_t b1) {
    asm volatile(
        "mma.sync.aligned.m16n8k16.row.col.f32.bf16.bf16.f32 "
        "{%0,%1,%2,%3}, {%4,%5,%6,%7}, {%8,%9}, {%0,%1,%2,%3};"
        : "+f"(c[0]), "+f"(c[1]), "+f"(c[2]), "+f"(c[3])
        : "r"(a.x), "r"(a.y), "r"(a.z), "r"(a.w), "r"(b0), "r"(b1));
}

// ---------------- prep: interpolate + split + pack W fragments ----------------
__global__ void prep_w(const float* __restrict__ W0, const float* __restrict__ W1,
                       const float* __restrict__ DoT)
{
    const int tap = blockIdx.x;
    const int b   = blockIdx.y;
    const float d = DoT[b], od = 1.0f - d;

    const int t    = threadIdx.x;
    const int kf   = t >> 7;
    const int mf   = (t >> 5) & 3;
    const int lane = t & 31;
    const int m    = mf * 16 + (lane >> 2);
    const int k    = kf * 16 + (lane & 3) * 2;

    float v[4][2];
    #pragma unroll
    for (int r = 0; r < 4; r++) {
        const int oc = m + (r & 1) * 8;
        const int ci = k + (r >> 1) * 8;
        const size_t g0 = (size_t)(oc * C_ + ci) * 9 + tap;
        v[r][0] = od * W0[g0] + d * W1[g0];
        v[r][1] = od * W0[g0 + 9] + d * W1[g0 + 9];
    }
    uint4 hi, lo;
    uint32_t* hp = &hi.x;
    uint32_t* lp = &lo.x;
    #pragma unroll
    for (int r = 0; r < 4; r++) split2(v[r][0], v[r][1], hp[r], lp[r]);

    const size_t base = ((((size_t)(b * 9 + tap) * 4 + kf) * 2) * 4 + mf) * 32 + lane;
    g_wfrag[base]       = hi;
    g_wfrag[base + 128] = lo;
}

// load one tap x kf block's fragments for this warp's oc-half (2 mf) into regs
#define LOADWF(AH, AL, base)                                   \
    do {                                                       \
        (AH)[0] = (base)[(oh * 2 + 0) * 32 + lane];            \
        (AH)[1] = (base)[(oh * 2 + 1) * 32 + lane];            \
        (AL)[0] = (base)[128 + (oh * 2 + 0) * 32 + lane];      \
        (AL)[1] = (base)[128 + (oh * 2 + 1) * 32 + lane];      \
    } while (0)

// compute one tap x kf block (4 cs x 6 MMAs) from resident regs
#define COMPUTE(AH, AL, ky, kx, kf)                                              \
    do {                                                                         \
        const uint32_t a_base = thr_base +                                       \
            (uint32_t)((row + (ky)) * ROWB + (kx) * 8 + (kf) * 4 * SLOTB);       \
        _Pragma("unroll")                                                        \
        for (int cs = 0; cs < 4; cs++) {                                         \
            const uint32_t ad = a_base + cs * 64;                                \
            uint32_t bh0, bh1, bl0, bl1;                                         \
            asm volatile("ld.shared.v2.b32 {%0,%1}, [%2];"                       \
                         : "=r"(bh0), "=r"(bh1) : "r"(ad));                      \
            asm volatile("ld.shared.v2.b32 {%0,%1}, [%2];"                       \
                         : "=r"(bl0), "=r"(bl1) : "r"(ad + IMGB));               \
            mma16816(acc[0][cs], (AH)[0], bh0, bh1);                             \
            mma16816(acc[1][cs], (AH)[1], bh0, bh1);                             \
            mma16816(acc[0][cs], (AL)[0], bh0, bh1);                             \
            mma16816(acc[1][cs], (AL)[1], bh0, bh1);                             \
            mma16816(acc[0][cs], (AH)[0], bl0, bl1);                             \
            mma16816(acc[1][cs], (AH)[1], bl0, bl1);                             \
        }                                                                        \
    } while (0)

// ---------------- main kernel ----------------
__global__ __launch_bounds__(THREADS, 1)
void conv_mma(const float* __restrict__ x, float* __restrict__ y)
{
    extern __shared__ char smem[];
    const uint32_t sx = smem_u32(smem);

    const int tid  = threadIdx.x;
    const int wid  = tid >> 5;
    const int lane = tid & 31;
    const int row  = wid & 7;        // tile row
    const int oh   = wid >> 3;       // oc half
    const int p_   = lane & 3;
    const int q    = lane >> 2;

    // CTA -> batch / tile range (144 CTAs = 16 batches x 9 CTAs; 16 tiles each)
    const int b    = blockIdx.x / 9;
    const int tib0 = (blockIdx.x % 9) * TPC;

    const float* xb = x + (size_t)b * C_ * NPIX;
    float* yb       = y + (size_t)b * C_ * NPIX;
    const uint4* wfb = g_wfrag + (size_t)b * 9 * 1024;

    const uint32_t thr_base = sx + (uint32_t)(p_ * SLOTB + q * 8);

    // weight double buffers (registers)
    uint4 ah0[2], al0[2], ah1[2], al1[2];
    LOADWF(ah0, al0, wfb);           // prologue: (tap0, kf0)

    for (int t = 0; t < TPC; t++) {
        const int tib = tib0 + t;
        const int py0 = (tib / 6) * TR;
        const int px0 = (tib % 6) * TC;

        // ---- serial fill (all 512 threads): fp32 halo -> bf16 hi/lo split ----
        __syncthreads();   // previous tile's reads complete
        for (int idx = tid; idx < 32 * HR * HC; idx += THREADS) {
            const int ci2 = idx / (HR * HC);
            const int rem = idx - ci2 * (HR * HC);
            const int r   = rem / HC;
            const int c   = rem - r * HC;
            const int gy  = py0 - 1 + r;
            const int gx  = px0 - 1 + c;
            float v0 = 0.f, v1 = 0.f;
            if ((unsigned)gy < H_ && (unsigned)gx < W_) {
                const float* p = xb + (size_t)(2 * ci2) * NPIX + gy * W_ + gx;
                v0 = p[0];
                v1 = p[NPIX];
            }
            uint32_t h2, l2;
            split2(v0, v1, h2, l2);
            const int kfi = ci2 >> 3, l = ci2 & 7, pp = l & 3, e = l >> 2;
            const uint32_t off = (uint32_t)((kfi * 4 + pp) * SLOTB + r * ROWB + c * 8 + e * 4);
            asm volatile("st.shared.b32 [%0], %1;" :: "r"(sx + off),        "r"(h2) : "memory");
            asm volatile("st.shared.b32 [%0], %1;" :: "r"(sx + IMGB + off), "r"(l2) : "memory");
        }
        __syncthreads();

        float acc[2][4][4];
        #pragma unroll
        for (int m = 0; m < 2; m++)
            #pragma unroll
            for (int cs = 0; cs < 4; cs++) {
                acc[m][cs][0] = 0.f; acc[m][cs][1] = 0.f;
                acc[m][cs][2] = 0.f; acc[m][cs][3] = 0.f;
            }

        // ---- mainloop: tap x kf with register-double-buffered weights ----
        for (int tap = 0; tap < 9; tap++) {
            const int ky = tap / 3;
            const int kx = tap - ky * 3;
            const uint4* wft  = wfb + tap * 1024;
            const uint4* wftn = wfb + (tap == 8 ? 0 : (tap + 1)) * 1024;

            LOADWF(ah1, al1, wft + 1 * 256);     // prefetch (tap, kf1)
            COMPUTE(ah0, al0, ky, kx, 0);
            LOADWF(ah0, al0, wft + 2 * 256);     // prefetch (tap, kf2)
            COMPUTE(ah1, al1, ky, kx, 1);
            LOADWF(ah1, al1, wft + 3 * 256);     // prefetch (tap, kf3)
            COMPUTE(ah0, al0, ky, kx, 2);
            LOADWF(ah0, al0, wftn);              // prefetch (tap+1, kf0) [wraps]
            COMPUTE(ah1, al1, ky, kx, 3);
        }

        // ---- epilogue ----
        const int gy = py0 + row;
        #pragma unroll
        for (int m = 0; m < 2; m++) {
            const int oc = (oh * 2 + m) * 16 + q;
            #pragma unroll
            for (int cs = 0; cs < 4; cs++) {
                const int gx = px0 + cs * 8 + 2 * p_;
                float2* o0 = (float2*)(yb + (size_t)oc * NPIX + gy * W_ + gx);
                *o0 = make_float2(acc[m][cs][0], acc[m][cs][1]);
                float2* o1 = (float2*)(yb + (size_t)(oc + 8) * NPIX + gy * W_ + gx);
                *o1 = make_float2(acc[m][cs][2], acc[m][cs][3]);
            }
        }
    }
}

// ---------------- launch ----------------
extern "C" void kernel_launch(void* const* d_in, const int* in_sizes, int n_in,
                              void* d_out, int out_size)
{
    const float* x   = (const float*)d_in[0];
    const float* DoT = (const float*)d_in[1];
    const float* W0  = (const float*)d_in[2];
    const float* W1  = (const float*)d_in[3];
    float* y = (float*)d_out;

    cudaFuncSetAttribute(conv_mma, cudaFuncAttributeMaxDynamicSharedMemorySize, SMEM_BYTES);

    prep_w<<<dim3(9, B_), 512>>>(W0, W1, DoT);
    // 2304 tiles = 144 CTAs x 16 tiles; 9 CTAs per batch, 1 CTA/SM, single wave
    conv_mma<<<144, THREADS, SMEM_BYTES>>>(x, y);
}